// round 2
// baseline (speedup 1.0000x reference)
#include <cuda_runtime.h>
#include <cuda_bf16.h>

// ---------------- problem constants ----------------
#define NNN     16384
#define MODIN   113
#define MODOUT  57

typedef unsigned long long u64;

// output layout (float offsets): readout | h_new | msg | hebbian
#define OUT_H    16384
#define OUT_MSG  (OUT_H + 4194304)
#define OUT_HEB  (OUT_MSG + 4194304)

__device__ __forceinline__ u64 pk2(float w) {
    u64 r; asm("mov.b64 %0, {%1, %1};" : "=l"(r) : "f"(w)); return r;
}
__device__ __forceinline__ void fma2(u64 &a, u64 b, u64 c) {
    asm("fma.rn.f32x2 %0, %1, %2, %0;" : "+l"(a) : "l"(b), "l"(c));
}
__device__ __forceinline__ float mytanh(float x) {
    float e = __expf(2.0f * x);
    return 1.0f - __fdividef(2.0f, e + 1.0f);
}
__device__ __forceinline__ float sigm(float x) {
    return __fdividef(1.0f, 1.0f + __expf(-x));
}

// ---------------- kernel A smem layout (float offsets) ----------------
#define OFF_SW1   0        // 64 x 97
#define OFF_SW2   6208     // 32 x 65 (pad)
#define OFF_MW1   8288     // 64 x 97 (96 used)
#define OFF_MW2   14496    // 32 x 65 (pad)
#define OFF_SB1   16576
#define OFF_SB2   16640
#define OFF_MB1   16672
#define OFF_MB2   16736
#define OFF_W1S   16768    // 32 x 113 per-neuron mod_w1
#define OFF_W2S   20384    // 32 x 57 per-neuron mod_w2 ([h][o])
#define OFF_MB1S  22208    // 32
#define OFF_MB2S  22240    // 57 (pad 64)
#define OFF_XIN   22304    // 113 x 8 batch-major mod input
#define OFF_HID   23208    // 32 x 8
#define OFF_OUTS  23464    // 57 x 8
#define OFF_SINT  23920    // 97 x 8
#define OFF_MINT  24696    // 96 x 8
#define OFF_SHST  25464    // 64 x 8
#define OFF_PSUM  25976    // 8 x 32 x 8
#define OFF_ACT   28024    // 200 sigmoids of OUTS[0:200]
#define OFF_CIDX  28224    // 16 ints
#define OFF_BIDX  28240    // 8 ints
#define SMEM_FLOATS 28248
#define SMEM_BYTES  (SMEM_FLOATS*4)

#define GRID_A 296

// partial GEMV: lane owns one output row (W element i at W[i*iStride]),
// accumulates all 8 batches packed as 4 f32x2, for i in [kbeg,kend)
__device__ __forceinline__ void gemv_part(const float* __restrict__ W, int iStride,
                                          const float* __restrict__ X,
                                          float* __restrict__ ps,
                                          int kbeg, int kend)
{
    u64 a0 = 0, a1 = 0, a2 = 0, a3 = 0;
    const float* w = W + kbeg * iStride;
    const u64* x = (const u64*)(X + kbeg * 8);
#pragma unroll 4
    for (int i = kbeg; i < kend; ++i) {
        u64 wp = pk2(*w); w += iStride;
        fma2(a0, wp, x[0]); fma2(a1, wp, x[1]);
        fma2(a2, wp, x[2]); fma2(a3, wp, x[3]);
        x += 4;
    }
    u64* pp = (u64*)ps;
    pp[0] = a0; pp[1] = a1; pp[2] = a2; pp[3] = a3;
}

__global__ void __launch_bounds__(256, 2)
cellA_kernel(const float* __restrict__ ccs,
             const float* __restrict__ hin,
             const float* __restrict__ pm,
             const float* __restrict__ dlog,
             const float* __restrict__ prim,
             const float* __restrict__ trc,
             const float* __restrict__ sw1g, const float* __restrict__ sb1g,
             const float* __restrict__ sw2g, const float* __restrict__ sb2g,
             const float* __restrict__ mw1g, const float* __restrict__ mb1g,
             const float* __restrict__ mw2g, const float* __restrict__ mb2g,
             const float* __restrict__ modw1, const float* __restrict__ modb1g,
             const float* __restrict__ modw2, const float* __restrict__ modb2g,
             const float* __restrict__ nidg,
             const int*   __restrict__ conn,
             const int*   __restrict__ bconn,
             float* __restrict__ outp)
{
    extern __shared__ float smf[];
    const int tid  = threadIdx.x;
    const int wid  = tid >> 5;
    const int lane = tid & 31;

    // ---- one-time per block: shared MLP weights into smem ----
    for (int i = tid; i < 1552; i += 256)   // state_w1 64x97 natural (odd stride)
        ((float4*)(smf + OFF_SW1))[i] = ((const float4*)sw1g)[i];
    for (int i = tid; i < 2048; i += 256) { // state_w2 [d][h] pad 65
        int d = i >> 6, h2 = i & 63;
        smf[OFF_SW2 + d*65 + h2] = sw2g[i];
    }
    for (int i = tid; i < 6144; i += 256) { // msg_w1 [h][i] pad 97
        int hh = i / 96, ii = i - hh*96;
        smf[OFF_MW1 + hh*97 + ii] = mw1g[i];
    }
    for (int i = tid; i < 2048; i += 256) { // msg_w2 [d][h] pad 65
        int d = i >> 6, h2 = i & 63;
        smf[OFF_MW2 + d*65 + h2] = mw2g[i];
    }
    if (tid < 64) smf[OFF_SB1 + tid] = sb1g[tid];
    if (tid < 32) smf[OFF_SB2 + tid] = sb2g[tid];
    if (tid < 64) smf[OFF_MB1 + tid] = mb1g[tid];
    if (tid < 32) smf[OFF_MB2 + tid] = mb2g[tid];
    __syncthreads();

    for (int n = blockIdx.x; n < NNN; n += GRID_A) {
        const int nc = n >> 8;
        const int c  = n & 255;
        const bool isb = (c >= 4 && c < 20);

        // ---- phase 0: per-neuron loads ----
        {
            const float4* w1src = (const float4*)(modw1 + (size_t)n * (32*MODIN));
            for (int i = tid; i < 904; i += 256) ((float4*)(smf + OFF_W1S))[i] = w1src[i];
            const float4* w2src = (const float4*)(modw2 + (size_t)n * (32*MODOUT));
            for (int i = tid; i < 456; i += 256) ((float4*)(smf + OFF_W2S))[i] = w2src[i];
            if (tid < 32) smf[OFF_MB1S + tid] = modb1g[n*32 + tid];
            if (tid < 57) smf[OFF_MB2S + tid] = modb2g[n*57 + tid];
            if (tid < 16) ((int*)(smf + OFF_CIDX))[tid] = conn[n*16 + tid];
            if (isb && tid < 8)
                ((int*)(smf + OFF_BIDX))[tid] = bconn[(nc*16 + (c-4))*8 + tid];

            // batch-major inputs: warp = batch, lane = d
            size_t nb = (size_t)wid * NNN + n;
            float hv = hin[nb*32 + lane];
            smf[OFF_XIN + (16+lane)*8 + wid] = hv;
            smf[OFF_SINT + lane*8 + wid] = hv;
            float pv = prim[nb*32 + lane];
            smf[OFF_XIN + (49+lane)*8 + wid] = pv;
            float nv = nidg[(size_t)n*32 + lane];
            smf[OFF_XIN + (81+lane)*8 + wid] = nv;
            smf[OFF_MINT + (64+lane)*8 + wid] = nv;
            if (lane < 16) smf[OFF_XIN + lane*8 + wid] = trc[nb*16 + lane];
            if (lane == 0) smf[OFF_XIN + 48*8 + wid] = dlog[nb];
        }
        __syncthreads();

        // ---- phase 1: mod layer1 O=32 K=113, K-split over 8 warps ----
        {
            int kb = (113*wid) >> 3, ke = (113*(wid+1)) >> 3;
            gemv_part(smf + OFF_W1S + lane*MODIN, 1, smf + OFF_XIN,
                      smf + OFF_PSUM + (wid*32 + lane)*8, kb, ke);
        }
        __syncthreads();
        {
            float s = smf[OFF_MB1S + (tid >> 3)];
#pragma unroll
            for (int w = 0; w < 8; w++) s += smf[OFF_PSUM + w*256 + tid];
            smf[OFF_HID + tid] = mytanh(s);
        }
        __syncthreads();

        // ---- phase 2: mod layer2 O=57 K=32 ----
        {
            int half = wid >> 2;                 // 0: outputs 0..31, 1: 32..56
            int kb = (wid & 3) * 8, ke = kb + 8;
            int o = half*32 + lane;
            if (half == 0 || lane < 25)
                gemv_part(smf + OFF_W2S + o, MODOUT, smf + OFF_HID,
                          smf + OFF_PSUM + (wid*32 + lane)*8, kb, ke);
        }
        __syncthreads();
        {
            for (int v = tid; v < 456; v += 256) {
                int o = v >> 3;
                float s = smf[OFF_MB2S + o];
                if (o < 32) {
#pragma unroll
                    for (int w = 0; w < 4; w++) s += smf[OFF_PSUM + w*256 + v];
                } else {
#pragma unroll
                    for (int w = 4; w < 8; w++) s += smf[OFF_PSUM + w*256 + (v-256)];
                }
                smf[OFF_OUTS + v] = s;
            }
        }
        __syncthreads();

        // ---- phase 3a: sigmoids (conn 0..15, border 16..23, decay 24) ----
        if (tid < 200) smf[OFF_ACT + tid] = sigm(smf[OFF_OUTS + tid]);
        __syncthreads();

        // ---- phase 3b: received + prim_new + decay into SINT/MINT ----
        {
            size_t bb = (size_t)wid * NNN;
            float acc = 0.0f;
#pragma unroll
            for (int k = 0; k < 16; k++) {
                int ci = ((const int*)(smf + OFF_CIDX))[k];
                acc = fmaf(pm[(bb + nc*256 + ci)*32 + lane],
                           smf[OFF_ACT + k*8 + wid], acc);
            }
            if (isb) {
#pragma unroll
                for (int kb2 = 0; kb2 < 8; kb2++) {
                    int bi = ((const int*)(smf + OFF_BIDX))[kb2];
                    acc = fmaf(pm[(bb + (bi>>4)*256 + 4 + (bi&15))*32 + lane],
                               smf[OFF_ACT + 128 + kb2*8 + wid], acc);
                }
            }
            if (c < 4) acc += ccs[wid*2048 + nc*32 + lane];
            smf[OFF_SINT + (32+lane)*8 + wid] = acc;
            smf[OFF_MINT + (32+lane)*8 + wid] = acc;
            float pnew = smf[OFF_XIN + (49+lane)*8 + wid] + smf[OFF_OUTS + (25+lane)*8 + wid];
            smf[OFF_SINT + (64+lane)*8 + wid] = pnew;
            if (lane == 0) smf[OFF_SINT + 96*8 + wid] = smf[OFF_ACT + 192 + wid];
        }
        __syncthreads();

        // ---- phase 4: state layer1 O=64 K=97 ----
        {
            int tile = wid & 1, s4 = wid >> 1;
            int kb = (97*s4) >> 2, ke = (97*(s4+1)) >> 2;
            int o = tile*32 + lane;
            gemv_part(smf + OFF_SW1 + o*97, 1, smf + OFF_SINT,
                      smf + OFF_PSUM + (wid*32 + lane)*8, kb, ke);
        }
        __syncthreads();
        {
            for (int v = tid; v < 512; v += 256) {
                int tile = v >> 8, r = v & 255;
                float s = smf[OFF_SB1 + (v >> 3)];
#pragma unroll
                for (int s4 = 0; s4 < 4; s4++) s += smf[OFF_PSUM + (2*s4 + tile)*256 + r];
                smf[OFF_SHST + v] = mytanh(s);
            }
        }
        __syncthreads();

        // ---- phase 5: state layer2 O=32 K=64, h_new ----
        {
            gemv_part(smf + OFF_SW2 + lane*65, 1, smf + OFF_SHST,
                      smf + OFF_PSUM + (wid*32 + lane)*8, wid*8, wid*8 + 8);
        }
        __syncthreads();
        {
            float s = smf[OFF_SB2 + (tid >> 3)];
#pragma unroll
            for (int w = 0; w < 8; w++) s += smf[OFF_PSUM + w*256 + tid];
            int b = tid & 7;
            float dec = smf[OFF_ACT + 192 + b];
            float hv  = smf[OFF_SINT + tid];
            smf[OFF_MINT + tid] = dec*hv + (1.0f - dec)*mytanh(s);
        }
        __syncthreads();

        // ---- phase 6: msg layer1 O=64 K=96 ----
        {
            int tile = wid & 1, s4 = wid >> 1;
            int kb = s4*24, ke = kb + 24;
            int o = tile*32 + lane;
            gemv_part(smf + OFF_MW1 + o*97, 1, smf + OFF_MINT,
                      smf + OFF_PSUM + (wid*32 + lane)*8, kb, ke);
        }
        __syncthreads();
        {
            for (int v = tid; v < 512; v += 256) {
                int tile = v >> 8, r = v & 255;
                float s = smf[OFF_MB1 + (v >> 3)];
#pragma unroll
                for (int s4 = 0; s4 < 4; s4++) s += smf[OFF_PSUM + (2*s4 + tile)*256 + r];
                smf[OFF_SHST + v] = mytanh(s);
            }
        }
        __syncthreads();

        // ---- phase 7: msg layer2 O=32 K=64 ----
        {
            gemv_part(smf + OFF_MW2 + lane*65, 1, smf + OFF_SHST,
                      smf + OFF_PSUM + (wid*32 + lane)*8, wid*8, wid*8 + 8);
        }
        __syncthreads();
        {
            float s = smf[OFF_MB2 + (tid >> 3)];
#pragma unroll
            for (int w = 0; w < 8; w++) s += smf[OFF_PSUM + w*256 + tid];
            smf[OFF_HID + tid] = mytanh(s);   // msg staging
        }
        __syncthreads();

        // ---- phase 8: writeback (warp=b, lane=d, coalesced) ----
        {
            size_t nb = (size_t)wid * NNN + n;
            outp[OUT_H   + nb*32 + lane] = smf[OFF_MINT + lane*8 + wid];
            outp[OUT_MSG + nb*32 + lane] = smf[OFF_HID  + lane*8 + wid];
        }
        __syncthreads();
    }
}

// ---------------- kernel B: hebbian + readout ----------------
#define SMEMB_BYTES (8448*4 + 4096*4)

__global__ void __launch_bounds__(256, 2)
cellB_kernel(const int* __restrict__ conn,
             const float* __restrict__ trc,
             float* __restrict__ outp)
{
    extern __shared__ float smb[];
    float* ms = smb;                    // 256 x 33
    int*   cs = (int*)(smb + 8448);     // 4096
    const int b  = blockIdx.x >> 6;
    const int nc = blockIdx.x & 63;
    const int tid = threadIdx.x;

    const float* msgg = outp + OUT_MSG + ((size_t)b*NNN + nc*256) * 32;
    for (int i = tid; i < 8192; i += 256)
        ms[(i >> 5)*33 + (i & 31)] = msgg[i];
    const int4* cg = (const int4*)(conn + nc*4096);
    for (int i = tid; i < 1024; i += 256) ((int4*)cs)[i] = cg[i];
    __syncthreads();

    const int c = tid;
    float me[32];
#pragma unroll
    for (int d = 0; d < 32; d++) me[d] = ms[c*33 + d];

    const size_t base = (size_t)b*NNN + nc*256 + c;
    float4 t4[4];
#pragma unroll
    for (int j = 0; j < 4; j++) t4[j] = ((const float4*)(trc + base*16))[j];

    float heb[16];
#pragma unroll
    for (int k = 0; k < 16; k++) {
        int ci = cs[c*16 + k];
        const float* nb = &ms[ci*33];
        float a0 = 0.0f, a1 = 0.0f;
#pragma unroll
        for (int d = 0; d < 32; d += 2) {
            a0 = fmaf(me[d],   nb[d],   a0);
            a1 = fmaf(me[d+1], nb[d+1], a1);
        }
        heb[k] = (a0 + a1) * 0.003125f;   // 0.1/32 * dot
    }
    float4* h4 = (float4*)(outp + OUT_HEB + base*16);
    h4[0] = make_float4(fmaf(0.9f,t4[0].x,heb[0]),  fmaf(0.9f,t4[0].y,heb[1]),
                        fmaf(0.9f,t4[0].z,heb[2]),  fmaf(0.9f,t4[0].w,heb[3]));
    h4[1] = make_float4(fmaf(0.9f,t4[1].x,heb[4]),  fmaf(0.9f,t4[1].y,heb[5]),
                        fmaf(0.9f,t4[1].z,heb[6]),  fmaf(0.9f,t4[1].w,heb[7]));
    h4[2] = make_float4(fmaf(0.9f,t4[2].x,heb[8]),  fmaf(0.9f,t4[2].y,heb[9]),
                        fmaf(0.9f,t4[2].z,heb[10]), fmaf(0.9f,t4[2].w,heb[11]));
    h4[3] = make_float4(fmaf(0.9f,t4[3].x,heb[12]), fmaf(0.9f,t4[3].y,heb[13]),
                        fmaf(0.9f,t4[3].z,heb[14]), fmaf(0.9f,t4[3].w,heb[15]));

    if (tid < 32) {
        float r = 0.25f * (ms[252*33 + tid] + ms[253*33 + tid] +
                           ms[254*33 + tid] + ms[255*33 + tid]);
        outp[b*2048 + nc*32 + tid] = r;
    }
}

extern "C" void kernel_launch(void* const* d_in, const int* in_sizes, int n_in,
                              void* d_out, int out_size)
{
    const float* ccs   = (const float*)d_in[0];
    const float* hin   = (const float*)d_in[1];
    const float* pm    = (const float*)d_in[2];
    const float* dlog  = (const float*)d_in[3];
    const float* prim  = (const float*)d_in[4];
    const float* trc   = (const float*)d_in[5];
    const float* sw1   = (const float*)d_in[6];
    const float* sb1   = (const float*)d_in[7];
    const float* sw2   = (const float*)d_in[8];
    const float* sb2   = (const float*)d_in[9];
    const float* mw1   = (const float*)d_in[10];
    const float* mb1   = (const float*)d_in[11];
    const float* mw2   = (const float*)d_in[12];
    const float* mb2   = (const float*)d_in[13];
    const float* modw1 = (const float*)d_in[14];
    const float* modb1 = (const float*)d_in[15];
    const float* modw2 = (const float*)d_in[16];
    const float* modb2 = (const float*)d_in[17];
    const float* nid   = (const float*)d_in[18];
    const int*   conn  = (const int*)d_in[19];
    const int*   bconn = (const int*)d_in[20];
    float* outp = (float*)d_out;

    cudaFuncSetAttribute(cellA_kernel, cudaFuncAttributeMaxDynamicSharedMemorySize, SMEM_BYTES);
    cudaFuncSetAttribute(cellB_kernel, cudaFuncAttributeMaxDynamicSharedMemorySize, SMEMB_BYTES);

    cellA_kernel<<<GRID_A, 256, SMEM_BYTES>>>(
        ccs, hin, pm, dlog, prim, trc,
        sw1, sb1, sw2, sb2, mw1, mb1, mw2, mb2,
        modw1, modb1, modw2, modb2, nid, conn, bconn, outp);

    cellB_kernel<<<512, 256, SMEMB_BYTES>>>(conn, trc, outp);
}